// round 11
// baseline (speedup 1.0000x reference)
#include <cuda_runtime.h>
#include <cuda_fp16.h>
#include <cstdint>

#define N_ENTITY 64368
#define N_REL    12
#define DIM      128
#define NB       8
#define N_ITEM   6924
#define EDGES    1000000
#define BATCH    128
#define SEQL     32

#define SCAN_BLOCKS 63   // 63 * 1024 = 64512 >= N_ENTITY

// ---------------- device scratch (static, allocation-free) ----------------
__device__ __align__(128) __half g_aggr[(size_t)N_ENTITY * DIM];  // 16.5 MB, L2-resident
__device__ __align__(128) float  g_nodes[(size_t)N_ENTITY * DIM]; // ~33 MB
__device__ __align__(128) float  g_u[BATCH * DIM];
__device__ int g_deg_in[N_ENTITY];    // in-degree (mean normalization)
__device__ int g_cnt_src[N_ENTITY];   // out-degree (sort key histogram)
__device__ int g_off[N_ENTITY + 1];
__device__ int g_cursor[N_ENTITY];
__device__ int g_sorted[EDGES];       // dst | type<<20, grouped by src
__device__ int g_part[SCAN_BLOCKS];

// ---------------- K1: zero aggr (fp16) + histograms ----------------
__global__ void k_init() {
    int i = blockIdx.x * blockDim.x + threadIdx.x;   // one uint4 = 8 halves
    if (i < N_ENTITY * DIM / 8)
        ((uint4*)g_aggr)[i] = make_uint4(0u, 0u, 0u, 0u);
    if (i < N_ENTITY) { g_deg_in[i] = 0; g_cnt_src[i] = 0; }
}

// ---------------- K2: histograms (out-deg for sort, in-deg for mean) --------
__global__ void k_hist(const int* __restrict__ src,
                       const int* __restrict__ dst) {
    int e = blockIdx.x * blockDim.x + threadIdx.x;
    if (e < EDGES) {
        atomicAdd(&g_cnt_src[src[e]], 1);
        atomicAdd(&g_deg_in[dst[e]], 1);
    }
}

// ---------------- block-wide inclusive scan helper ----------------
__device__ __forceinline__ int block_incl_scan(int v, int t) {
    __shared__ int warp_tot[32];
    int lane = t & 31, wid = t >> 5;
#pragma unroll
    for (int o = 1; o < 32; o <<= 1) {
        int n = __shfl_up_sync(0xffffffffu, v, o);
        if (lane >= o) v += n;
    }
    if (lane == 31) warp_tot[wid] = v;
    __syncthreads();
    if (wid == 0) {
        int w = warp_tot[lane];
#pragma unroll
        for (int o = 1; o < 32; o <<= 1) {
            int n = __shfl_up_sync(0xffffffffu, w, o);
            if (lane >= o) w += n;
        }
        warp_tot[lane] = w;
    }
    __syncthreads();
    if (wid > 0) v += warp_tot[wid - 1];
    return v;
}

// ---------------- K3a: per-block partial sums of out-degree ----------------
__global__ void k_partial() {
    int idx = blockIdx.x * 1024 + threadIdx.x;
    int v = (idx < N_ENTITY) ? g_cnt_src[idx] : 0;
    int incl = block_incl_scan(v, threadIdx.x);
    if (threadIdx.x == 1023) g_part[blockIdx.x] = incl;
}

// ---------------- K3b: offsets (each block re-scans the 63 partials) --------
__global__ void k_offsets() {
    int b = blockIdx.x, t = threadIdx.x;
    int idx = b * 1024 + t;
    int v = (idx < N_ENTITY) ? g_cnt_src[idx] : 0;
    int incl = block_incl_scan(v, t);
    __syncthreads();

    int pv = (t < SCAN_BLOCKS) ? g_part[t] : 0;
    int pincl = block_incl_scan(pv, t);

    __shared__ int base_s;
    if (b == 0) { if (t == 0) base_s = 0; }
    else if (t == b - 1) base_s = pincl;
    __syncthreads();

    int excl = base_s + incl - v;
    if (idx < N_ENTITY) {
        g_off[idx]    = excl;
        g_cursor[idx] = excl;
    }
    if (b == SCAN_BLOCKS - 1 && t == 1023) g_off[N_ENTITY] = EDGES;
}

// ---------------- K4: scatter edges grouped by src ----------------
__global__ void k_scatter(const int* __restrict__ src,
                          const int* __restrict__ dst,
                          const int* __restrict__ type) {
    int e = blockIdx.x * blockDim.x + threadIdx.x;
    if (e < EDGES) {
        int s = src[e];
        int pos = atomicAdd(&g_cursor[s], 1);
        g_sorted[pos] = dst[e] | (type[e] << 20);
    }
}

// ---------------- K5: warp-per-src message + fp16x2 vector reduction --------
// Two edges per warp iteration: lanes 0-15 handle edge e, lanes 16-31 edge e+1.
// Each lane owns 8 consecutive floats of the 128-dim message -> one
// red.global.add.noftz.v4.f16x2 (16B, 8 halves) per lane per edge.
__global__ void k_msg(const float* __restrict__ basis,
                      const float* __restrict__ att) {
    __shared__ float att_s[N_REL * NB];
    if (threadIdx.x < N_REL * NB) att_s[threadIdx.x] = att[threadIdx.x];
    __syncthreads();

    int gw    = (blockIdx.x * blockDim.x + threadIdx.x) >> 5;
    int lane  = threadIdx.x & 31;
    int sub   = lane >> 4;       // 0 or 1: which edge of the pair
    int lane8 = lane & 15;       // float-chunk index (8 floats each)
    if (gw >= N_ENTITY) return;

    int start = g_off[gw];
    int end   = g_off[gw + 1];
    if (start == end) return;

    // basis rows for this src: each lane holds its 8 floats of every base
    float4 bv[NB][2];
#pragma unroll
    for (int b = 0; b < NB; b++) {
        const float* row = basis + ((size_t)b * N_ENTITY + gw) * DIM + lane8 * 8;
        bv[b][0] = *(const float4*)(row);
        bv[b][1] = *(const float4*)(row + 4);
    }

    for (int e = start; e < end; e += 2) {
        int idx = e + sub;
        bool act = idx < end;
        int p = g_sorted[act ? idx : start];
        int dst = p & 0xFFFFF;
        const float* a = att_s + (p >> 20) * NB;

        float4 m0 = make_float4(0.f, 0.f, 0.f, 0.f);
        float4 m1 = make_float4(0.f, 0.f, 0.f, 0.f);
#pragma unroll
        for (int b = 0; b < NB; b++) {
            float c = a[b];
            m0.x += c * bv[b][0].x; m0.y += c * bv[b][0].y;
            m0.z += c * bv[b][0].z; m0.w += c * bv[b][0].w;
            m1.x += c * bv[b][1].x; m1.y += c * bv[b][1].y;
            m1.z += c * bv[b][1].z; m1.w += c * bv[b][1].w;
        }

        __half2 h0 = __floats2half2_rn(m0.x, m0.y);
        __half2 h1 = __floats2half2_rn(m0.z, m0.w);
        __half2 h2 = __floats2half2_rn(m1.x, m1.y);
        __half2 h3 = __floats2half2_rn(m1.z, m1.w);
        unsigned r0 = *(unsigned*)&h0, r1 = *(unsigned*)&h1;
        unsigned r2 = *(unsigned*)&h2, r3 = *(unsigned*)&h3;

        if (act) {
            __half* q = g_aggr + (size_t)dst * DIM + lane8 * 8;
            asm volatile("red.global.add.noftz.v4.f16x2 [%0], {%1, %2, %3, %4};"
                         :: "l"(q), "r"(r0), "r"(r1), "r"(r2), "r"(r3)
                         : "memory");
        }
    }
}

// ---------------- K6: nodes = aggr/max(deg,1) + root + bias ----------------
__global__ void k_final(const float* __restrict__ root,
                        const float* __restrict__ bias) {
    int tid = blockIdx.x * blockDim.x + threadIdx.x;
    if (tid >= N_ENTITY * (DIM / 4)) return;
    int n = tid >> 5;
    int c = tid & 31;

    int deg = g_deg_in[n];
    float inv = 1.0f / (float)(deg > 0 ? deg : 1);

    const __half2* ah = (const __half2*)(g_aggr + (size_t)n * DIM + c * 4);
    float2 fa = __half22float2(ah[0]);
    float2 fb = __half22float2(ah[1]);

    float4 r4 = *(const float4*)(root + (size_t)n * DIM + c * 4);
    float4 b4 = *(const float4*)(bias + c * 4);
    float4 o;
    o.x = fa.x * inv + r4.x + b4.x;
    o.y = fa.y * inv + r4.y + b4.y;
    o.z = fb.x * inv + r4.z + b4.z;
    o.w = fb.y * inv + r4.w + b4.w;
    *(float4*)(g_nodes + (size_t)n * DIM + c * 4) = o;
}

// ---------------- K7: attention pooling (one block per batch row) ------------
__global__ void k_pool(const int* __restrict__ seed_ids,
                       const int* __restrict__ seed_len,
                       const float* __restrict__ attn_a,
                       const float* __restrict__ attn_b) {
    __shared__ float h[SEQL][DIM];
    __shared__ float e_sh[SEQL];
    __shared__ float red[4];

    int b = blockIdx.x;
    int d = threadIdx.x;   // 128 threads
    int len = seed_len[b];

    for (int l = 0; l < SEQL; l++) {
        int id = seed_ids[b * SEQL + l];
        h[l][d] = g_nodes[(size_t)id * DIM + d];
    }
    __syncthreads();

    float bd = attn_b[d];
    for (int l = 0; l < SEQL; l++) {
        float t = 0.f;
#pragma unroll 8
        for (int k = 0; k < DIM; k++)
            t += h[l][k] * __ldg(&attn_a[k * DIM + d]);
        float val = tanhf(t) * bd;
#pragma unroll
        for (int o = 16; o > 0; o >>= 1)
            val += __shfl_down_sync(0xffffffff, val, o);
        if ((d & 31) == 0) red[d >> 5] = val;
        __syncthreads();
        if (d == 0) e_sh[l] = red[0] + red[1] + red[2] + red[3];
        __syncthreads();
    }

    float u = 0.f;
    if (len > 0) {
        float m = -1e30f;
        for (int l = 0; l < len; l++) m = fmaxf(m, e_sh[l]);
        float ssum = 0.f;
        for (int l = 0; l < len; l++) ssum += expf(e_sh[l] - m);
        float rinv = 1.f / ssum;
        for (int l = 0; l < len; l++)
            u += expf(e_sh[l] - m) * rinv * h[l][d];
    }
    g_u[b * DIM + d] = u;
}

// ---------------- K8: scores = u @ nodes[:N_ITEM]^T + out_bias ---------------
#define SCORES_SMEM (BATCH * DIM * 4 + 32 * 33 * 16)

__global__ void k_scores(const float* __restrict__ out_bias,
                         float* __restrict__ out) {
    extern __shared__ float smem[];
    float4* u_sh4 = (float4*)smem;                        // [128][32] float4
    float4* n_sh4 = (float4*)(smem + BATCH * DIM);        // [32][33] float4 (padded)

    int t  = threadIdx.x;                                  // 256 threads
    int i0 = blockIdx.x * 32;

    const float4* gu4 = (const float4*)g_u;
    for (int idx = t; idx < BATCH * DIM / 4; idx += 256)
        u_sh4[idx] = gu4[idx];

    const float4* gn4 = (const float4*)g_nodes;
    for (int idx = t; idx < 32 * 32; idx += 256) {
        int r = idx >> 5, c = idx & 31;
        n_sh4[r * 33 + c] = gn4[(size_t)(i0 + r) * 32 + c];
    }
    __syncthreads();

    int tx = t & 31;     // item within tile
    int ty = t >> 5;     // 0..7, b = ty + 8*j

    float acc[16];
#pragma unroll
    for (int j = 0; j < 16; j++) acc[j] = 0.f;

    for (int d4 = 0; d4 < 32; d4++) {
        float4 nv = n_sh4[tx * 33 + d4];
#pragma unroll
        for (int j = 0; j < 16; j++) {
            float4 uv = u_sh4[(ty + 8 * j) * 32 + d4];
            acc[j] += nv.x * uv.x + nv.y * uv.y + nv.z * uv.z + nv.w * uv.w;
        }
    }

    int i = i0 + tx;
    if (i < N_ITEM) {
        float ob = out_bias[i];
#pragma unroll
        for (int j = 0; j < 16; j++)
            out[(size_t)(ty + 8 * j) * N_ITEM + i] = acc[j] + ob;
    }
}

// ---------------- launch (single stream) ----------------
extern "C" void kernel_launch(void* const* d_in, const int* in_sizes, int n_in,
                              void* d_out, int out_size) {
    const int*   edge_idx  = (const int*)d_in[0];
    const int*   edge_type = (const int*)d_in[1];
    const int*   seed_ids  = (const int*)d_in[2];
    const int*   seed_len  = (const int*)d_in[3];
    // d_in[4] = labels (unused for scores)
    const float* basis     = (const float*)d_in[5];
    const float* att       = (const float*)d_in[6];
    const float* root      = (const float*)d_in[7];
    const float* rgcn_bias = (const float*)d_in[8];
    const float* attn_a    = (const float*)d_in[9];
    const float* attn_b    = (const float*)d_in[10];
    const float* out_bias  = (const float*)d_in[11];
    float* out = (float*)d_out;

    const int* src = edge_idx;
    const int* dst = edge_idx + EDGES;

    cudaFuncSetAttribute(k_scores, cudaFuncAttributeMaxDynamicSharedMemorySize,
                         SCORES_SMEM);

    k_init<<<(N_ENTITY * 32 + 255) / 256, 256>>>();
    k_hist<<<(EDGES + 255) / 256, 256>>>(src, dst);
    k_partial<<<SCAN_BLOCKS, 1024>>>();
    k_offsets<<<SCAN_BLOCKS, 1024>>>();
    k_scatter<<<(EDGES + 255) / 256, 256>>>(src, dst, edge_type);
    k_msg<<<(N_ENTITY * 32 + 255) / 256, 256>>>(basis, att);
    k_final<<<(N_ENTITY * 32 + 255) / 256, 256>>>(root, rgcn_bias);
    k_pool<<<BATCH, DIM>>>(seed_ids, seed_len, attn_a, attn_b);
    k_scores<<<(N_ITEM + 31) / 32, 256, SCORES_SMEM>>>(out_bias, out);
}

// round 12
// speedup vs baseline: 1.3518x; 1.3518x over previous
#include <cuda_runtime.h>
#include <cstdint>

#define N_ENTITY 64368
#define N_REL    12
#define DIM      128
#define NB       8
#define N_ITEM   6924
#define N_ITEM_PAD 6944            // 217*32, padding rows stay zero
#define EDGES    1000000
#define BATCH    128
#define SEQL     32

// ---------------- device scratch (static, allocation-free) ----------------
__device__ __align__(128) float g_aggr[(size_t)N_ITEM * DIM];      // 3.5 MB, L2-resident
__device__ __align__(128) float g_nodes[(size_t)N_ITEM_PAD * DIM]; // 3.6 MB
__device__ __align__(128) float g_u[BATCH * DIM];
__device__ int g_deg[N_ITEM];
__device__ int g_est[EDGES];    // src | type<<17  (src < 2^17, type < 12)
__device__ int g_edst[EDGES];   // dst < N_ITEM
__device__ int g_cnt;

// ---------------- K1: zero aggr + deg + counter ----------------
__global__ void k_init() {
    int i = blockIdx.x * blockDim.x + threadIdx.x;
    if (i < N_ITEM * DIM / 4)
        ((float4*)g_aggr)[i] = make_float4(0.f, 0.f, 0.f, 0.f);
    if (i < N_ITEM) g_deg[i] = 0;
    if (i == 0) g_cnt = 0;
}

// ---------------- K2: filter edges with dst < N_ITEM, compact + deg ---------
__global__ void k_filter(const int* __restrict__ src,
                         const int* __restrict__ dst,
                         const int* __restrict__ type) {
    int e = blockIdx.x * blockDim.x + threadIdx.x;
    if (e >= EDGES) return;
    int d = dst[e];
    if (d < N_ITEM) {
        int pos = atomicAdd(&g_cnt, 1);
        g_est[pos]  = src[e] | (type[e] << 17);
        g_edst[pos] = d;
        atomicAdd(&g_deg[d], 1);
    }
}

// ---------------- K3: warp-per-edge message + fp32 v4 reduction -------------
// msg[d] = sum_b att[type,b] * basis[b,src,d]; red.v4.f32 into g_aggr[dst]
__global__ void k_msg(const float* __restrict__ basis,
                      const float* __restrict__ att) {
    __shared__ float att_s[N_REL * NB];
    if (threadIdx.x < N_REL * NB) att_s[threadIdx.x] = att[threadIdx.x];
    __syncthreads();

    int wid  = (blockIdx.x * blockDim.x + threadIdx.x) >> 5;
    int lane = threadIdx.x & 31;
    int nw   = (gridDim.x * blockDim.x) >> 5;
    int cnt  = g_cnt;

    for (int e = wid; e < cnt; e += nw) {
        int st  = g_est[e];
        int d   = g_edst[e];
        int s   = st & 0x1FFFF;
        const float* a = att_s + (st >> 17) * NB;

        // 8 independent coalesced 512B row loads (this lane's float4 of each)
        float4 bv[NB];
#pragma unroll
        for (int b = 0; b < NB; b++)
            bv[b] = *(const float4*)(basis + ((size_t)b * N_ENTITY + s) * DIM + lane * 4);

        float4 m = make_float4(0.f, 0.f, 0.f, 0.f);
#pragma unroll
        for (int b = 0; b < NB; b++) {
            float c = a[b];
            m.x += c * bv[b].x; m.y += c * bv[b].y;
            m.z += c * bv[b].z; m.w += c * bv[b].w;
        }

        float* q = g_aggr + (size_t)d * DIM + lane * 4;
        asm volatile("red.global.add.v4.f32 [%0], {%1, %2, %3, %4};"
                     :: "l"(q), "f"(m.x), "f"(m.y), "f"(m.z), "f"(m.w)
                     : "memory");
    }
}

// ---------------- K4: nodes = aggr/max(deg,1) + root + bias (items only) ----
__global__ void k_final(const float* __restrict__ root,
                        const float* __restrict__ bias) {
    int tid = blockIdx.x * blockDim.x + threadIdx.x;
    if (tid >= N_ITEM * (DIM / 4)) return;
    int n = tid >> 5;
    int c = tid & 31;

    int deg = g_deg[n];
    float inv = 1.0f / (float)(deg > 0 ? deg : 1);
    float4 a  = *(const float4*)(g_aggr + (size_t)n * DIM + c * 4);
    float4 r4 = *(const float4*)(root + (size_t)n * DIM + c * 4);
    float4 b4 = *(const float4*)(bias + c * 4);
    float4 o;
    o.x = a.x * inv + r4.x + b4.x;
    o.y = a.y * inv + r4.y + b4.y;
    o.z = a.z * inv + r4.z + b4.z;
    o.w = a.w * inv + r4.w + b4.w;
    *(float4*)(g_nodes + (size_t)n * DIM + c * 4) = o;
}

// ---------------- K5: attention pooling (one block per batch row) ------------
__global__ void k_pool(const int* __restrict__ seed_ids,
                       const int* __restrict__ seed_len,
                       const float* __restrict__ attn_a,
                       const float* __restrict__ attn_b) {
    __shared__ float h[SEQL][DIM];
    __shared__ float e_sh[SEQL];
    __shared__ float red[4];

    int b = blockIdx.x;
    int d = threadIdx.x;   // 128 threads
    int len = seed_len[b];

    for (int l = 0; l < SEQL; l++) {
        int id = seed_ids[b * SEQL + l];     // id < N_ITEM
        h[l][d] = g_nodes[(size_t)id * DIM + d];
    }
    __syncthreads();

    float bd = attn_b[d];
    for (int l = 0; l < SEQL; l++) {
        float t = 0.f;
#pragma unroll 8
        for (int k = 0; k < DIM; k++)
            t += h[l][k] * __ldg(&attn_a[k * DIM + d]);
        float val = tanhf(t) * bd;
#pragma unroll
        for (int o = 16; o > 0; o >>= 1)
            val += __shfl_down_sync(0xffffffff, val, o);
        if ((d & 31) == 0) red[d >> 5] = val;
        __syncthreads();
        if (d == 0) e_sh[l] = red[0] + red[1] + red[2] + red[3];
        __syncthreads();
    }

    float u = 0.f;
    if (len > 0) {
        float m = -1e30f;
        for (int l = 0; l < len; l++) m = fmaxf(m, e_sh[l]);
        float ssum = 0.f;
        for (int l = 0; l < len; l++) ssum += expf(e_sh[l] - m);
        float rinv = 1.f / ssum;
        for (int l = 0; l < len; l++)
            u += expf(e_sh[l] - m) * rinv * h[l][d];
    }
    g_u[b * DIM + d] = u;
}

// ---------------- K6: scores = u @ nodes[:N_ITEM]^T + out_bias ---------------
#define SCORES_SMEM (BATCH * DIM * 4 + 32 * 33 * 16)

__global__ void k_scores(const float* __restrict__ out_bias,
                         float* __restrict__ out) {
    extern __shared__ float smem[];
    float4* u_sh4 = (float4*)smem;                        // [128][32] float4
    float4* n_sh4 = (float4*)(smem + BATCH * DIM);        // [32][33] float4 (padded)

    int t  = threadIdx.x;                                  // 256 threads
    int i0 = blockIdx.x * 32;

    const float4* gu4 = (const float4*)g_u;
    for (int idx = t; idx < BATCH * DIM / 4; idx += 256)
        u_sh4[idx] = gu4[idx];

    const float4* gn4 = (const float4*)g_nodes;
    for (int idx = t; idx < 32 * 32; idx += 256) {
        int r = idx >> 5, c = idx & 31;
        n_sh4[r * 33 + c] = gn4[(size_t)(i0 + r) * 32 + c];  // i0+r < N_ITEM_PAD
    }
    __syncthreads();

    int tx = t & 31;     // item within tile
    int ty = t >> 5;     // 0..7, b = ty + 8*j

    float acc[16];
#pragma unroll
    for (int j = 0; j < 16; j++) acc[j] = 0.f;

    for (int d4 = 0; d4 < 32; d4++) {
        float4 nv = n_sh4[tx * 33 + d4];
#pragma unroll
        for (int j = 0; j < 16; j++) {
            float4 uv = u_sh4[(ty + 8 * j) * 32 + d4];
            acc[j] += nv.x * uv.x + nv.y * uv.y + nv.z * uv.z + nv.w * uv.w;
        }
    }

    int i = i0 + tx;
    if (i < N_ITEM) {
        float ob = out_bias[i];
#pragma unroll
        for (int j = 0; j < 16; j++)
            out[(size_t)(ty + 8 * j) * N_ITEM + i] = acc[j] + ob;
    }
}

// ---------------- launch ----------------
extern "C" void kernel_launch(void* const* d_in, const int* in_sizes, int n_in,
                              void* d_out, int out_size) {
    const int*   edge_idx  = (const int*)d_in[0];
    const int*   edge_type = (const int*)d_in[1];
    const int*   seed_ids  = (const int*)d_in[2];
    const int*   seed_len  = (const int*)d_in[3];
    // d_in[4] = labels (unused for scores)
    const float* basis     = (const float*)d_in[5];
    const float* att       = (const float*)d_in[6];
    const float* root      = (const float*)d_in[7];
    const float* rgcn_bias = (const float*)d_in[8];
    const float* attn_a    = (const float*)d_in[9];
    const float* attn_b    = (const float*)d_in[10];
    const float* out_bias  = (const float*)d_in[11];
    float* out = (float*)d_out;

    const int* src = edge_idx;
    const int* dst = edge_idx + EDGES;

    cudaFuncSetAttribute(k_scores, cudaFuncAttributeMaxDynamicSharedMemorySize,
                         SCORES_SMEM);

    k_init<<<(N_ITEM * 32 + 255) / 256, 256>>>();
    k_filter<<<(EDGES + 255) / 256, 256>>>(src, dst, edge_type);
    k_msg<<<1184, 256>>>(basis, att);                 // 148 SMs x 8 blocks, grid-stride
    k_final<<<(N_ITEM * 32 + 255) / 256, 256>>>(root, rgcn_bias);
    k_pool<<<BATCH, DIM>>>(seed_ids, seed_len, attn_a, attn_b);
    k_scores<<<(N_ITEM + 31) / 32, 256, SCORES_SMEM>>>(out_bias, out);
}

// round 13
// speedup vs baseline: 1.4192x; 1.0498x over previous
#include <cuda_runtime.h>
#include <cstdint>

#define N_ENTITY 64368
#define N_REL    12
#define DIM      128
#define NB       8
#define N_ITEM   6924
#define N_ITEM_PAD 6944            // 217*32, padding rows stay zero
#define EDGES    1000000
#define BATCH    128
#define SEQL     32

// ---------------- device scratch (static, allocation-free) ----------------
__device__ __align__(128) float g_aggr[(size_t)N_ITEM * DIM];      // 3.5 MB, L2-resident
__device__ __align__(128) float g_nodes[(size_t)N_ITEM_PAD * DIM]; // 3.6 MB
__device__ __align__(128) float g_u[BATCH * DIM];
__device__ int g_deg[N_ITEM];

// ---------------- K1: zero aggr + deg ----------------
__global__ void k_init() {
    int i = blockIdx.x * blockDim.x + threadIdx.x;
    if (i < N_ITEM * DIM / 4)
        ((float4*)g_aggr)[i] = make_float4(0.f, 0.f, 0.f, 0.f);
    if (i < N_ITEM) g_deg[i] = 0;
}

// ---------------- K2: fused filter + message + fp32 v4 reduction ------------
// Warp takes 32 consecutive edges, ballots dst<N_ITEM (~3.4 hits), then the
// whole warp computes msg = sum_b att[type,b]*basis[b,src] for each hit
// (two hits in flight for MLP) and red.v4.f32's it into g_aggr[dst].
__global__ void k_msg(const int* __restrict__ src,
                      const int* __restrict__ dst,
                      const int* __restrict__ type,
                      const float* __restrict__ basis,
                      const float* __restrict__ att) {
    __shared__ float att_s[N_REL * NB];
    if (threadIdx.x < N_REL * NB) att_s[threadIdx.x] = att[threadIdx.x];
    __syncthreads();

    const unsigned FULL = 0xffffffffu;
    int wid  = (blockIdx.x * blockDim.x + threadIdx.x) >> 5;
    int lane = threadIdx.x & 31;
    int nw   = (gridDim.x * blockDim.x) >> 5;
    const int NCHUNK = EDGES / 32;   // 31250, EDGES divisible by 32

    for (int ch = wid; ch < NCHUNK; ch += nw) {
        int e = ch * 32 + lane;
        int d = dst[e];
        bool act = d < N_ITEM;
        unsigned mask = __ballot_sync(FULL, act);
        if (!mask) continue;

        int s = 0, t = 0;
        if (act) {
            s = src[e];
            t = type[e];
            atomicAdd(&g_deg[d], 1);
        }

        while (mask) {
            int l0 = __ffs(mask) - 1; mask &= mask - 1;
            int l1 = -1;
            if (mask) { l1 = __ffs(mask) - 1; mask &= mask - 1; }

            int s0 = __shfl_sync(FULL, s, l0);
            int t0 = __shfl_sync(FULL, t, l0);
            int d0 = __shfl_sync(FULL, d, l0);
            int s1 = __shfl_sync(FULL, s, l1 < 0 ? l0 : l1);
            int t1 = __shfl_sync(FULL, t, l1 < 0 ? l0 : l1);
            int d1 = __shfl_sync(FULL, d, l1 < 0 ? l0 : l1);

            // 16 independent coalesced 512B row loads in flight
            float4 b0[NB], b1[NB];
#pragma unroll
            for (int b = 0; b < NB; b++)
                b0[b] = *(const float4*)(basis + ((size_t)b * N_ENTITY + s0) * DIM + lane * 4);
            if (l1 >= 0) {
#pragma unroll
                for (int b = 0; b < NB; b++)
                    b1[b] = *(const float4*)(basis + ((size_t)b * N_ENTITY + s1) * DIM + lane * 4);
            }

            const float* a0 = att_s + t0 * NB;
            float4 m0 = make_float4(0.f, 0.f, 0.f, 0.f);
#pragma unroll
            for (int b = 0; b < NB; b++) {
                float c = a0[b];
                m0.x += c * b0[b].x; m0.y += c * b0[b].y;
                m0.z += c * b0[b].z; m0.w += c * b0[b].w;
            }
            float* q0 = g_aggr + (size_t)d0 * DIM + lane * 4;
            asm volatile("red.global.add.v4.f32 [%0], {%1, %2, %3, %4};"
                         :: "l"(q0), "f"(m0.x), "f"(m0.y), "f"(m0.z), "f"(m0.w)
                         : "memory");

            if (l1 >= 0) {
                const float* a1 = att_s + t1 * NB;
                float4 m1 = make_float4(0.f, 0.f, 0.f, 0.f);
#pragma unroll
                for (int b = 0; b < NB; b++) {
                    float c = a1[b];
                    m1.x += c * b1[b].x; m1.y += c * b1[b].y;
                    m1.z += c * b1[b].z; m1.w += c * b1[b].w;
                }
                float* q1 = g_aggr + (size_t)d1 * DIM + lane * 4;
                asm volatile("red.global.add.v4.f32 [%0], {%1, %2, %3, %4};"
                             :: "l"(q1), "f"(m1.x), "f"(m1.y), "f"(m1.z), "f"(m1.w)
                             : "memory");
            }
        }
    }
}

// ---------------- K3: nodes = aggr/max(deg,1) + root + bias (items only) ----
__global__ void k_final(const float* __restrict__ root,
                        const float* __restrict__ bias) {
    int tid = blockIdx.x * blockDim.x + threadIdx.x;
    if (tid >= N_ITEM * (DIM / 4)) return;
    int n = tid >> 5;
    int c = tid & 31;

    int deg = g_deg[n];
    float inv = 1.0f / (float)(deg > 0 ? deg : 1);
    float4 a  = *(const float4*)(g_aggr + (size_t)n * DIM + c * 4);
    float4 r4 = *(const float4*)(root + (size_t)n * DIM + c * 4);
    float4 b4 = *(const float4*)(bias + c * 4);
    float4 o;
    o.x = a.x * inv + r4.x + b4.x;
    o.y = a.y * inv + r4.y + b4.y;
    o.z = a.z * inv + r4.z + b4.z;
    o.w = a.w * inv + r4.w + b4.w;
    *(float4*)(g_nodes + (size_t)n * DIM + c * 4) = o;
}

// ---------------- K4: attention pooling (one block per batch row) ------------
__global__ void k_pool(const int* __restrict__ seed_ids,
                       const int* __restrict__ seed_len,
                       const float* __restrict__ attn_a,
                       const float* __restrict__ attn_b) {
    __shared__ float h[SEQL][DIM];
    __shared__ float e_sh[SEQL];
    __shared__ float red[4];

    int b = blockIdx.x;
    int d = threadIdx.x;   // 128 threads
    int len = seed_len[b];

    for (int l = 0; l < SEQL; l++) {
        int id = seed_ids[b * SEQL + l];     // id < N_ITEM
        h[l][d] = g_nodes[(size_t)id * DIM + d];
    }
    __syncthreads();

    float bd = attn_b[d];
    for (int l = 0; l < SEQL; l++) {
        float t = 0.f;
#pragma unroll 8
        for (int k = 0; k < DIM; k++)
            t += h[l][k] * __ldg(&attn_a[k * DIM + d]);
        float val = tanhf(t) * bd;
#pragma unroll
        for (int o = 16; o > 0; o >>= 1)
            val += __shfl_down_sync(0xffffffff, val, o);
        if ((d & 31) == 0) red[d >> 5] = val;
        __syncthreads();
        if (d == 0) e_sh[l] = red[0] + red[1] + red[2] + red[3];
        __syncthreads();
    }

    float u = 0.f;
    if (len > 0) {
        float m = -1e30f;
        for (int l = 0; l < len; l++) m = fmaxf(m, e_sh[l]);
        float ssum = 0.f;
        for (int l = 0; l < len; l++) ssum += expf(e_sh[l] - m);
        float rinv = 1.f / ssum;
        for (int l = 0; l < len; l++)
            u += expf(e_sh[l] - m) * rinv * h[l][d];
    }
    g_u[b * DIM + d] = u;
}

// ---------------- K5: scores = u @ nodes[:N_ITEM]^T + out_bias ---------------
#define SCORES_SMEM (BATCH * DIM * 4 + 32 * 33 * 16)

__global__ void k_scores(const float* __restrict__ out_bias,
                         float* __restrict__ out) {
    extern __shared__ float smem[];
    float4* u_sh4 = (float4*)smem;                        // [128][32] float4
    float4* n_sh4 = (float4*)(smem + BATCH * DIM);        // [32][33] float4 (padded)

    int t  = threadIdx.x;                                  // 256 threads
    int i0 = blockIdx.x * 32;

    const float4* gu4 = (const float4*)g_u;
    for (int idx = t; idx < BATCH * DIM / 4; idx += 256)
        u_sh4[idx] = gu4[idx];

    const float4* gn4 = (const float4*)g_nodes;
    for (int idx = t; idx < 32 * 32; idx += 256) {
        int r = idx >> 5, c = idx & 31;
        n_sh4[r * 33 + c] = gn4[(size_t)(i0 + r) * 32 + c];  // i0+r < N_ITEM_PAD
    }
    __syncthreads();

    int tx = t & 31;     // item within tile
    int ty = t >> 5;     // 0..7, b = ty + 8*j

    float acc[16];
#pragma unroll
    for (int j = 0; j < 16; j++) acc[j] = 0.f;

    for (int d4 = 0; d4 < 32; d4++) {
        float4 nv = n_sh4[tx * 33 + d4];
#pragma unroll
        for (int j = 0; j < 16; j++) {
            float4 uv = u_sh4[(ty + 8 * j) * 32 + d4];
            acc[j] += nv.x * uv.x + nv.y * uv.y + nv.z * uv.z + nv.w * uv.w;
        }
    }

    int i = i0 + tx;
    if (i < N_ITEM) {
        float ob = out_bias[i];
#pragma unroll
        for (int j = 0; j < 16; j++)
            out[(size_t)(ty + 8 * j) * N_ITEM + i] = acc[j] + ob;
    }
}

// ---------------- launch ----------------
extern "C" void kernel_launch(void* const* d_in, const int* in_sizes, int n_in,
                              void* d_out, int out_size) {
    const int*   edge_idx  = (const int*)d_in[0];
    const int*   edge_type = (const int*)d_in[1];
    const int*   seed_ids  = (const int*)d_in[2];
    const int*   seed_len  = (const int*)d_in[3];
    // d_in[4] = labels (unused for scores)
    const float* basis     = (const float*)d_in[5];
    const float* att       = (const float*)d_in[6];
    const float* root      = (const float*)d_in[7];
    const float* rgcn_bias = (const float*)d_in[8];
    const float* attn_a    = (const float*)d_in[9];
    const float* attn_b    = (const float*)d_in[10];
    const float* out_bias  = (const float*)d_in[11];
    float* out = (float*)d_out;

    const int* src = edge_idx;
    const int* dst = edge_idx + EDGES;

    cudaFuncSetAttribute(k_scores, cudaFuncAttributeMaxDynamicSharedMemorySize,
                         SCORES_SMEM);

    k_init<<<(N_ITEM * 32 + 255) / 256, 256>>>();
    k_msg<<<1184, 256>>>(src, dst, edge_type, basis, att);  // 148 SMs x 8 blocks
    k_final<<<(N_ITEM * 32 + 255) / 256, 256>>>(root, rgcn_bias);
    k_pool<<<BATCH, DIM>>>(seed_ids, seed_len, attn_a, attn_b);
    k_scores<<<(N_ITEM + 31) / 32, 256, SCORES_SMEM>>>(out_bias, out);
}

// round 15
// speedup vs baseline: 1.8603x; 1.3108x over previous
#include <cuda_runtime.h>
#include <cstdint>

#define N_ENTITY 64368
#define N_REL    12
#define DIM      128
#define NB       8
#define N_ITEM   6924
#define N_ITEM_PAD 6944            // 217*32, padding rows stay zero
#define EDGES    1000000
#define BATCH    128
#define SEQL     32

// ---------------- device scratch (static, allocation-free) ----------------
__device__ __align__(128) float g_aggr[(size_t)N_ITEM * DIM];      // 3.5 MB, L2-resident
__device__ __align__(128) float g_nodes[(size_t)N_ITEM_PAD * DIM]; // 3.6 MB
__device__ __align__(128) float g_u[BATCH * DIM];
__device__ __align__(128) float g_e[BATCH * SEQL];
__device__ int g_deg[N_ITEM];

// ---------------- K1: zero aggr + deg ----------------
__global__ void k_init() {
    int i = blockIdx.x * blockDim.x + threadIdx.x;
    if (i < N_ITEM * DIM / 4)
        ((float4*)g_aggr)[i] = make_float4(0.f, 0.f, 0.f, 0.f);
    if (i < N_ITEM) g_deg[i] = 0;
}

// ---------------- K2: fused filter + message + fp32 v4 reduction ------------
__global__ void k_msg(const int* __restrict__ src,
                      const int* __restrict__ dst,
                      const int* __restrict__ type,
                      const float* __restrict__ basis,
                      const float* __restrict__ att) {
    __shared__ float att_s[N_REL * NB];
    if (threadIdx.x < N_REL * NB) att_s[threadIdx.x] = att[threadIdx.x];
    __syncthreads();

    const unsigned FULL = 0xffffffffu;
    int wid  = (blockIdx.x * blockDim.x + threadIdx.x) >> 5;
    int lane = threadIdx.x & 31;
    int nw   = (gridDim.x * blockDim.x) >> 5;
    const int NCHUNK = EDGES / 32;   // 31250

    for (int ch = wid; ch < NCHUNK; ch += nw) {
        int e = ch * 32 + lane;
        int d = dst[e];
        bool act = d < N_ITEM;
        unsigned mask = __ballot_sync(FULL, act);
        if (!mask) continue;

        int s = 0, t = 0;
        if (act) {
            s = src[e];
            t = type[e];
            atomicAdd(&g_deg[d], 1);
        }

        while (mask) {
            int l0 = __ffs(mask) - 1; mask &= mask - 1;
            int l1 = -1;
            if (mask) { l1 = __ffs(mask) - 1; mask &= mask - 1; }

            int s0 = __shfl_sync(FULL, s, l0);
            int t0 = __shfl_sync(FULL, t, l0);
            int d0 = __shfl_sync(FULL, d, l0);
            int s1 = __shfl_sync(FULL, s, l1 < 0 ? l0 : l1);
            int t1 = __shfl_sync(FULL, t, l1 < 0 ? l0 : l1);
            int d1 = __shfl_sync(FULL, d, l1 < 0 ? l0 : l1);

            float4 b0[NB], b1[NB];
#pragma unroll
            for (int b = 0; b < NB; b++)
                b0[b] = *(const float4*)(basis + ((size_t)b * N_ENTITY + s0) * DIM + lane * 4);
            if (l1 >= 0) {
#pragma unroll
                for (int b = 0; b < NB; b++)
                    b1[b] = *(const float4*)(basis + ((size_t)b * N_ENTITY + s1) * DIM + lane * 4);
            }

            const float* a0 = att_s + t0 * NB;
            float4 m0 = make_float4(0.f, 0.f, 0.f, 0.f);
#pragma unroll
            for (int b = 0; b < NB; b++) {
                float c = a0[b];
                m0.x += c * b0[b].x; m0.y += c * b0[b].y;
                m0.z += c * b0[b].z; m0.w += c * b0[b].w;
            }
            float* q0 = g_aggr + (size_t)d0 * DIM + lane * 4;
            asm volatile("red.global.add.v4.f32 [%0], {%1, %2, %3, %4};"
                         :: "l"(q0), "f"(m0.x), "f"(m0.y), "f"(m0.z), "f"(m0.w)
                         : "memory");

            if (l1 >= 0) {
                const float* a1 = att_s + t1 * NB;
                float4 m1 = make_float4(0.f, 0.f, 0.f, 0.f);
#pragma unroll
                for (int b = 0; b < NB; b++) {
                    float c = a1[b];
                    m1.x += c * b1[b].x; m1.y += c * b1[b].y;
                    m1.z += c * b1[b].z; m1.w += c * b1[b].w;
                }
                float* q1 = g_aggr + (size_t)d1 * DIM + lane * 4;
                asm volatile("red.global.add.v4.f32 [%0], {%1, %2, %3, %4};"
                             :: "l"(q1), "f"(m1.x), "f"(m1.y), "f"(m1.z), "f"(m1.w)
                             : "memory");
            }
        }
    }
}

// ---------------- K3: nodes = aggr/max(deg,1) + root + bias (items only) ----
__global__ void k_final(const float* __restrict__ root,
                        const float* __restrict__ bias) {
    int tid = blockIdx.x * blockDim.x + threadIdx.x;
    if (tid >= N_ITEM * (DIM / 4)) return;
    int n = tid >> 5;
    int c = tid & 31;

    int deg = g_deg[n];
    float inv = 1.0f / (float)(deg > 0 ? deg : 1);
    float4 a  = *(const float4*)(g_aggr + (size_t)n * DIM + c * 4);
    float4 r4 = *(const float4*)(root + (size_t)n * DIM + c * 4);
    float4 b4 = *(const float4*)(bias + c * 4);
    float4 o;
    o.x = a.x * inv + r4.x + b4.x;
    o.y = a.y * inv + r4.y + b4.y;
    o.z = a.z * inv + r4.z + b4.z;
    o.w = a.w * inv + r4.w + b4.w;
    *(float4*)(g_nodes + (size_t)n * DIM + c * 4) = o;
}

// ---------------- K4: attention scores e[b,l] = tanh(h@A)@b -----------------
// 512 blocks x 256 threads; block caches A (64KB) + attn_b in smem; each of
// its 8 warps computes one (b,l) pair. One LDS.128 of A per k per lane.
#define ATT_SMEM (DIM * DIM * 4 + 8 * DIM * 4 + DIM * 4)

__global__ void k_att(const int* __restrict__ seed_ids,
                      const float* __restrict__ attn_a,
                      const float* __restrict__ attn_b) {
    extern __shared__ float sm[];
    float* A_s = sm;                   // [128][128]
    float* h_s = sm + DIM * DIM;       // [8][128]
    float* b_s = h_s + 8 * DIM;        // [128]

    int t = threadIdx.x;
    float4* A4 = (float4*)A_s;
    const float4* gA4 = (const float4*)attn_a;
    for (int i = t; i < DIM * DIM / 4; i += 256) A4[i] = gA4[i];
    if (t < DIM) b_s[t] = attn_b[t];

    int w = t >> 5, lane = t & 31;
    int p = blockIdx.x * 8 + w;        // p < 4096 = BATCH*SEQL exactly
    int id = seed_ids[p];              // seed_ids is [B][L] row-major
    ((float4*)(h_s + w * DIM))[lane] =
        ((const float4*)(g_nodes + (size_t)id * DIM))[lane];
    __syncthreads();

    const float* hw = h_s + w * DIM;
    float4 acc = make_float4(0.f, 0.f, 0.f, 0.f);
#pragma unroll 4
    for (int k = 0; k < DIM; k++) {
        float hk = hw[k];                              // broadcast
        float4 a4 = ((float4*)(A_s + k * DIM))[lane];  // conflict-free
        acc.x += hk * a4.x; acc.y += hk * a4.y;
        acc.z += hk * a4.z; acc.w += hk * a4.w;
    }

    float4 bb = ((float4*)b_s)[lane];
    float val = tanhf(acc.x) * bb.x + tanhf(acc.y) * bb.y +
                tanhf(acc.z) * bb.z + tanhf(acc.w) * bb.w;
#pragma unroll
    for (int o = 16; o > 0; o >>= 1)
        val += __shfl_down_sync(0xffffffffu, val, o);
    if (lane == 0) g_e[p] = val;
}

// ---------------- K5: softmax + weighted sum -> u[b] ------------------------
__global__ void k_pool2(const int* __restrict__ seed_ids,
                        const int* __restrict__ seed_len) {
    __shared__ float e_sh[SEQL];
    __shared__ int   ids[SEQL];

    int b = blockIdx.x;
    int d = threadIdx.x;   // 128
    int len = seed_len[b];

    if (d < SEQL) {
        e_sh[d] = g_e[b * SEQL + d];
        ids[d]  = seed_ids[b * SEQL + d];
    }
    __syncthreads();

    float u = 0.f;
    if (len > 0) {
        float m = -1e30f;
        for (int l = 0; l < len; l++) m = fmaxf(m, e_sh[l]);
        float ssum = 0.f;
        for (int l = 0; l < len; l++) ssum += expf(e_sh[l] - m);
        float rinv = 1.f / ssum;
        for (int l = 0; l < len; l++)
            u += expf(e_sh[l] - m) * rinv * g_nodes[(size_t)ids[l] * DIM + d];
    }
    g_u[b * DIM + d] = u;
}

// ---------------- K6: scores = u @ nodes[:N_ITEM]^T + out_bias ---------------
#define SCORES_SMEM (BATCH * DIM * 4 + 32 * 33 * 16)

__global__ void k_scores(const float* __restrict__ out_bias,
                         float* __restrict__ out) {
    extern __shared__ float smem[];
    float4* u_sh4 = (float4*)smem;                        // [128][32] float4
    float4* n_sh4 = (float4*)(smem + BATCH * DIM);        // [32][33] float4 (padded)

    int t  = threadIdx.x;                                  // 256 threads
    int i0 = blockIdx.x * 32;

    const float4* gu4 = (const float4*)g_u;
    for (int idx = t; idx < BATCH * DIM / 4; idx += 256)
        u_sh4[idx] = gu4[idx];

    const float4* gn4 = (const float4*)g_nodes;
    for (int idx = t; idx < 32 * 32; idx += 256) {
        int r = idx >> 5, c = idx & 31;
        n_sh4[r * 33 + c] = gn4[(size_t)(i0 + r) * 32 + c];  // i0+r < N_ITEM_PAD
    }
    __syncthreads();

    int tx = t & 31;     // item within tile
    int ty = t >> 5;     // 0..7, b = ty + 8*j

    float acc[16];
#pragma unroll
    for (int j = 0; j < 16; j++) acc[j] = 0.f;

    for (int d4 = 0; d4 < 32; d4++) {
        float4 nv = n_sh4[tx * 33 + d4];
#pragma unroll
        for (int j = 0; j < 16; j++) {
            float4 uv = u_sh4[(ty + 8 * j) * 32 + d4];
            acc[j] += nv.x * uv.x + nv.y * uv.y + nv.z * uv.z + nv.w * uv.w;
        }
    }

    int i = i0 + tx;
    if (i < N_ITEM) {
        float ob = out_bias[i];
#pragma unroll
        for (int j = 0; j < 16; j++)
            out[(size_t)(ty + 8 * j) * N_ITEM + i] = acc[j] + ob;
    }
}

// ---------------- launch ----------------
extern "C" void kernel_launch(void* const* d_in, const int* in_sizes, int n_in,
                              void* d_out, int out_size) {
    const int*   edge_idx  = (const int*)d_in[0];
    const int*   edge_type = (const int*)d_in[1];
    const int*   seed_ids  = (const int*)d_in[2];
    const int*   seed_len  = (const int*)d_in[3];
    // d_in[4] = labels (unused for scores)
    const float* basis     = (const float*)d_in[5];
    const float* att       = (const float*)d_in[6];
    const float* root      = (const float*)d_in[7];
    const float* rgcn_bias = (const float*)d_in[8];
    const float* attn_a    = (const float*)d_in[9];
    const float* attn_b    = (const float*)d_in[10];
    const float* out_bias  = (const float*)d_in[11];
    float* out = (float*)d_out;

    const int* src = edge_idx;
    const int* dst = edge_idx + EDGES;

    cudaFuncSetAttribute(k_scores, cudaFuncAttributeMaxDynamicSharedMemorySize,
                         SCORES_SMEM);
    cudaFuncSetAttribute(k_att, cudaFuncAttributeMaxDynamicSharedMemorySize,
                         ATT_SMEM);

    k_init<<<(N_ITEM * 32 + 255) / 256, 256>>>();
    k_msg<<<1184, 256>>>(src, dst, edge_type, basis, att);  // 148 SMs x 8 blocks
    k_final<<<(N_ITEM * 32 + 255) / 256, 256>>>(root, rgcn_bias);
    k_att<<<BATCH * SEQL / 8, 256, ATT_SMEM>>>(seed_ids, attn_a, attn_b);
    k_pool2<<<BATCH, DIM>>>(seed_ids, seed_len);
    k_scores<<<(N_ITEM + 31) / 32, 256, SCORES_SMEM>>>(out_bias, out);
}

// round 17
// speedup vs baseline: 3.0351x; 1.6315x over previous
#include <cuda_runtime.h>
#include <cstdint>

#define N_ENTITY 64368
#define N_REL    12
#define DIM      128
#define NB       8
#define N_ITEM   6924
#define N_ITEM_PAD 6944            // 217*32, padding rows stay zero
#define EDGES    1000000
#define BATCH    128
#define SEQL     32

#define SCAN_BLOCKS 63             // 63*1024 = 64512 >= N_ENTITY

// ---------------- device scratch (static, allocation-free) ----------------
__device__ __align__(128) float g_aggr[(size_t)N_ITEM * DIM];      // 3.5 MB, L2-resident
__device__ __align__(128) float g_nodes[(size_t)N_ITEM_PAD * DIM]; // 3.6 MB
__device__ __align__(128) float g_u[BATCH * DIM];
__device__ __align__(128) float g_e[BATCH * SEQL];
__device__ int g_deg[N_ITEM];
__device__ int g_cnt_src[N_ENTITY];
__device__ int g_off[N_ENTITY + 1];
__device__ int g_cursor[N_ENTITY];
__device__ int g_sorted[EDGES];    // dst | type<<13 (dst<8192), grouped by src
__device__ int g_part[SCAN_BLOCKS];

// ---------------- K1: zero aggr + deg + src histogram ----------------
__global__ void k_init() {
    int i = blockIdx.x * blockDim.x + threadIdx.x;
    if (i < N_ITEM * DIM / 4)
        ((float4*)g_aggr)[i] = make_float4(0.f, 0.f, 0.f, 0.f);
    if (i < N_ITEM) g_deg[i] = 0;
    if (i < N_ENTITY) g_cnt_src[i] = 0;
}

// ---------------- K2: histogram of src over filtered edges (+deg) -----------
__global__ void k_hist(const int* __restrict__ src,
                       const int* __restrict__ dst) {
    int e = blockIdx.x * blockDim.x + threadIdx.x;
    if (e >= EDGES) return;
    int d = dst[e];
    if (d < N_ITEM) {
        atomicAdd(&g_cnt_src[src[e]], 1);
        atomicAdd(&g_deg[d], 1);
    }
}

// ---------------- block-wide inclusive scan helper ----------------
__device__ __forceinline__ int block_incl_scan(int v, int t) {
    __shared__ int warp_tot[32];
    int lane = t & 31, wid = t >> 5;
#pragma unroll
    for (int o = 1; o < 32; o <<= 1) {
        int n = __shfl_up_sync(0xffffffffu, v, o);
        if (lane >= o) v += n;
    }
    if (lane == 31) warp_tot[wid] = v;
    __syncthreads();
    if (wid == 0) {
        int w = warp_tot[lane];
#pragma unroll
        for (int o = 1; o < 32; o <<= 1) {
            int n = __shfl_up_sync(0xffffffffu, w, o);
            if (lane >= o) w += n;
        }
        warp_tot[lane] = w;
    }
    __syncthreads();
    if (wid > 0) v += warp_tot[wid - 1];
    return v;
}

// ---------------- K3a: per-block partial sums ----------------
__global__ void k_partial() {
    int idx = blockIdx.x * 1024 + threadIdx.x;
    int v = (idx < N_ENTITY) ? g_cnt_src[idx] : 0;
    int incl = block_incl_scan(v, threadIdx.x);
    if (threadIdx.x == 1023) g_part[blockIdx.x] = incl;
}

// ---------------- K3b: offsets (each block re-scans the 63 partials) --------
__global__ void k_offsets() {
    int b = blockIdx.x, t = threadIdx.x;
    int idx = b * 1024 + t;
    int v = (idx < N_ENTITY) ? g_cnt_src[idx] : 0;
    int incl = block_incl_scan(v, t);
    __syncthreads();

    int pv = (t < SCAN_BLOCKS) ? g_part[t] : 0;
    int pincl = block_incl_scan(pv, t);

    __shared__ int base_s;
    if (b == 0) { if (t == 0) base_s = 0; }
    else if (t == b - 1) base_s = pincl;
    __syncthreads();

    int excl = base_s + incl - v;
    if (idx < N_ENTITY) {
        g_off[idx]    = excl;
        g_cursor[idx] = excl;
    }
    if (b == SCAN_BLOCKS - 1 && t == 1023) g_off[N_ENTITY] = excl + v;
}

// ---------------- K4: scatter filtered edges grouped by src ----------------
__global__ void k_scatter(const int* __restrict__ src,
                          const int* __restrict__ dst,
                          const int* __restrict__ type) {
    int e = blockIdx.x * blockDim.x + threadIdx.x;
    if (e >= EDGES) return;
    int d = dst[e];
    if (d < N_ITEM) {
        int s = src[e];
        int pos = atomicAdd(&g_cursor[s], 1);
        g_sorted[pos] = d | (type[e] << 13);
    }
}

// ---------------- K5: warp-per-src message + fp32 v4 reduction --------------
// Load the 8 basis rows of src ONCE into registers, reuse for all its
// filtered outgoing edges (avg multiplicity ~2.1 -> halves basis traffic).
__global__ void k_msg(const float* __restrict__ basis,
                      const float* __restrict__ att) {
    __shared__ float att_s[N_REL * NB];
    if (threadIdx.x < N_REL * NB) att_s[threadIdx.x] = att[threadIdx.x];
    __syncthreads();

    int s    = (blockIdx.x * blockDim.x + threadIdx.x) >> 5;  // entity id
    int lane = threadIdx.x & 31;
    if (s >= N_ENTITY) return;

    int start = g_off[s];
    int end   = g_off[s + 1];
    if (start == end) return;

    float4 bv[NB];
#pragma unroll
    for (int b = 0; b < NB; b++)
        bv[b] = *(const float4*)(basis + ((size_t)b * N_ENTITY + s) * DIM + lane * 4);

    for (int e = start; e < end; e++) {
        int p = g_sorted[e];
        int d = p & 0x1FFF;
        const float* a = att_s + (p >> 13) * NB;

        float4 m = make_float4(0.f, 0.f, 0.f, 0.f);
#pragma unroll
        for (int b = 0; b < NB; b++) {
            float c = a[b];
            m.x += c * bv[b].x; m.y += c * bv[b].y;
            m.z += c * bv[b].z; m.w += c * bv[b].w;
        }
        float* q = g_aggr + (size_t)d * DIM + lane * 4;
        asm volatile("red.global.add.v4.f32 [%0], {%1, %2, %3, %4};"
                     :: "l"(q), "f"(m.x), "f"(m.y), "f"(m.z), "f"(m.w)
                     : "memory");
    }
}

// ---------------- K6: nodes = aggr/max(deg,1) + root + bias (items only) ----
__global__ void k_final(const float* __restrict__ root,
                        const float* __restrict__ bias) {
    int tid = blockIdx.x * blockDim.x + threadIdx.x;
    if (tid >= N_ITEM * (DIM / 4)) return;
    int n = tid >> 5;
    int c = tid & 31;

    int deg = g_deg[n];
    float inv = 1.0f / (float)(deg > 0 ? deg : 1);
    float4 a  = *(const float4*)(g_aggr + (size_t)n * DIM + c * 4);
    float4 r4 = *(const float4*)(root + (size_t)n * DIM + c * 4);
    float4 b4 = *(const float4*)(bias + c * 4);
    float4 o;
    o.x = a.x * inv + r4.x + b4.x;
    o.y = a.y * inv + r4.y + b4.y;
    o.z = a.z * inv + r4.z + b4.z;
    o.w = a.w * inv + r4.w + b4.w;
    *(float4*)(g_nodes + (size_t)n * DIM + c * 4) = o;
}

// ---------------- K7: attention scores as register-tiled GEMM ---------------
// e[p] = tanh(h_p @ A) @ b over 4096 rows. 64 blocks x 64 rows each.
// smem: A [128][128] + H transposed [128][68 pad] + b + e partials.
// Thread micro-tile: 4 rows x 8 cols; per k: 3 LDS.128 -> 32 FMA.
#define HT_STRIDE 68
#define ATT_SMEM ((DIM * DIM + DIM * HT_STRIDE + DIM + 64) * 4)

__global__ void k_att(const int* __restrict__ seed_ids,
                      const float* __restrict__ attn_a,
                      const float* __restrict__ attn_b) {
    extern __shared__ float sm[];
    float* A_s = sm;                           // [128][128]
    float* Ht  = sm + DIM * DIM;               // [128][68]
    float* b_s = Ht + DIM * HT_STRIDE;         // [128]
    float* e_s = b_s + DIM;                    // [64]

    int t = threadIdx.x;   // 256

    // load A (coalesced float4)
    float4* A4 = (float4*)A_s;
    const float4* gA4 = (const float4*)attn_a;
#pragma unroll
    for (int i = 0; i < 16; i++) A4[t + i * 256] = gA4[t + i * 256];
    if (t < DIM) b_s[t] = attn_b[t];
    if (t < 64) e_s[t] = 0.f;

    // load 64 H rows transposed: 4 threads per row, 8 float4 each
    {
        int r  = t >> 2;               // 0..63
        int k0 = (t & 3) * 32;         // starting k
        int id = seed_ids[blockIdx.x * 64 + r];
        const float4* hrow = (const float4*)(g_nodes + (size_t)id * DIM);
#pragma unroll
        for (int j = 0; j < 8; j++) {
            float4 v = hrow[k0 / 4 + j];
            int k = k0 + j * 4;
            Ht[(k + 0) * HT_STRIDE + r] = v.x;
            Ht[(k + 1) * HT_STRIDE + r] = v.y;
            Ht[(k + 2) * HT_STRIDE + r] = v.z;
            Ht[(k + 3) * HT_STRIDE + r] = v.w;
        }
    }
    __syncthreads();

    int rowg = t & 15;       // 16 groups of 4 rows
    int colg = t >> 4;       // 16 groups of 8 cols
    int r0 = rowg * 4;
    int c0 = colg * 8;

    float acc[4][8];
#pragma unroll
    for (int i = 0; i < 4; i++)
#pragma unroll
        for (int j = 0; j < 8; j++) acc[i][j] = 0.f;

#pragma unroll 4
    for (int k = 0; k < DIM; k++) {
        float4 hv = *(const float4*)(Ht + k * HT_STRIDE + r0);
        float4 a0 = *(const float4*)(A_s + k * DIM + c0);
        float4 a1 = *(const float4*)(A_s + k * DIM + c0 + 4);
        float h[4] = {hv.x, hv.y, hv.z, hv.w};
        float av[8] = {a0.x, a0.y, a0.z, a0.w, a1.x, a1.y, a1.z, a1.w};
#pragma unroll
        for (int i = 0; i < 4; i++)
#pragma unroll
            for (int j = 0; j < 8; j++)
                acc[i][j] += h[i] * av[j];
    }

    // epilogue: tanh, dot with b, reduce across col-groups
#pragma unroll
    for (int i = 0; i < 4; i++) {
        float part = 0.f;
#pragma unroll
        for (int j = 0; j < 8; j++)
            part += tanhf(acc[i][j]) * b_s[c0 + j];
        part += __shfl_down_sync(0xffffffffu, part, 16);   // combine colg pair
        if ((t & 31) < 16)
            atomicAdd(&e_s[r0 + i], part);
    }
    __syncthreads();

    if (t < 64) g_e[blockIdx.x * 64 + t] = e_s[t];
}

// ---------------- K8: softmax + weighted sum -> u[b] ------------------------
__global__ void k_pool2(const int* __restrict__ seed_ids,
                        const int* __restrict__ seed_len) {
    __shared__ float e_sh[SEQL];
    __shared__ int   ids[SEQL];

    int b = blockIdx.x;
    int d = threadIdx.x;   // 128
    int len = seed_len[b];

    if (d < SEQL) {
        e_sh[d] = g_e[b * SEQL + d];
        ids[d]  = seed_ids[b * SEQL + d];
    }
    __syncthreads();

    float u = 0.f;
    if (len > 0) {
        float m = -1e30f;
        for (int l = 0; l < len; l++) m = fmaxf(m, e_sh[l]);
        float ssum = 0.f;
        for (int l = 0; l < len; l++) ssum += expf(e_sh[l] - m);
        float rinv = 1.f / ssum;
        for (int l = 0; l < len; l++)
            u += expf(e_sh[l] - m) * rinv * g_nodes[(size_t)ids[l] * DIM + d];
    }
    g_u[b * DIM + d] = u;
}

// ---------------- K9: scores = u @ nodes[:N_ITEM]^T + out_bias ---------------
#define SCORES_SMEM (BATCH * DIM * 4 + 32 * 33 * 16)

__global__ void k_scores(const float* __restrict__ out_bias,
                         float* __restrict__ out) {
    extern __shared__ float smem[];
    float4* u_sh4 = (float4*)smem;                        // [128][32] float4
    float4* n_sh4 = (float4*)(smem + BATCH * DIM);        // [32][33] float4 (padded)

    int t  = threadIdx.x;                                  // 256 threads
    int i0 = blockIdx.x * 32;

    const float4* gu4 = (const float4*)g_u;
    for (int idx = t; idx < BATCH * DIM / 4; idx += 256)
        u_sh4[idx] = gu4[idx];

    const float4* gn4 = (const float4*)g_nodes;
    for (int idx = t; idx < 32 * 32; idx += 256) {
        int r = idx >> 5, c = idx & 31;
        n_sh4[r * 33 + c] = gn4[(size_t)(i0 + r) * 32 + c];  // i0+r < N_ITEM_PAD
    }
    __syncthreads();

    int tx = t & 31;     // item within tile
    int ty = t >> 5;     // 0..7, b = ty + 8*j

    float acc[16];
#pragma unroll
    for (int j = 0; j < 16; j++) acc[j] = 0.f;

    for (int d4 = 0; d4 < 32; d4++) {
        float4 nv = n_sh4[tx * 33 + d4];
#pragma unroll
        for (int j = 0; j < 16; j++) {
            float4 uv = u_sh4[(ty + 8 * j) * 32 + d4];
            acc[j] += nv.x * uv.x + nv.y * uv.y + nv.z * uv.z + nv.w * uv.w;
        }
    }

    int i = i0 + tx;
    if (i < N_ITEM) {
        float ob = out_bias[i];
#pragma unroll
        for (int j = 0; j < 16; j++)
            out[(size_t)(ty + 8 * j) * N_ITEM + i] = acc[j] + ob;
    }
}

// ---------------- launch ----------------
extern "C" void kernel_launch(void* const* d_in, const int* in_sizes, int n_in,
                              void* d_out, int out_size) {
    const int*   edge_idx  = (const int*)d_in[0];
    const int*   edge_type = (const int*)d_in[1];
    const int*   seed_ids  = (const int*)d_in[2];
    const int*   seed_len  = (const int*)d_in[3];
    // d_in[4] = labels (unused for scores)
    const float* basis     = (const float*)d_in[5];
    const float* att       = (const float*)d_in[6];
    const float* root      = (const float*)d_in[7];
    const float* rgcn_bias = (const float*)d_in[8];
    const float* attn_a    = (const float*)d_in[9];
    const float* attn_b    = (const float*)d_in[10];
    const float* out_bias  = (const float*)d_in[11];
    float* out = (float*)d_out;

    const int* src = edge_idx;
    const int* dst = edge_idx + EDGES;

    cudaFuncSetAttribute(k_scores, cudaFuncAttributeMaxDynamicSharedMemorySize,
                         SCORES_SMEM);
    cudaFuncSetAttribute(k_att, cudaFuncAttributeMaxDynamicSharedMemorySize,
                         ATT_SMEM);

    k_init<<<(N_ITEM * 32 + 255) / 256, 256>>>();
    k_hist<<<(EDGES + 255) / 256, 256>>>(src, dst);
    k_partial<<<SCAN_BLOCKS, 1024>>>();
    k_offsets<<<SCAN_BLOCKS, 1024>>>();
    k_scatter<<<(EDGES + 255) / 256, 256>>>(src, dst, edge_type);
    k_msg<<<(N_ENTITY * 32 + 255) / 256, 256>>>(basis, att);
    k_final<<<(N_ITEM * 32 + 255) / 256, 256>>>(root, rgcn_bias);
    k_att<<<BATCH * SEQL / 64, 256, ATT_SMEM>>>(seed_ids, attn_a, attn_b);
    k_pool2<<<BATCH, DIM>>>(seed_ids, seed_len);
    k_scores<<<(N_ITEM + 31) / 32, 256, SCORES_SMEM>>>(out_bias, out);
}